// round 1
// baseline (speedup 1.0000x reference)
#include <cuda_runtime.h>
#include <cstdint>
#include <math.h>

// Problem constants (fixed shapes for this problem instance)
#define DD   1024
#define SS   2048
#define NH   8
#define HDIM 128

// ---------------- scratch (static device globals; no allocation) -------------
__device__ float g_XLN[8192 * 1024];
__device__ float g_X2 [8192 * 1024];
__device__ float g_QKV[8192 * 3072];
__device__ float g_SC [(size_t)NH * SS * SS];   // one batch chunk of scores (128 MB)
__device__ float g_CTX[8192 * 1024];

// ---------------- helpers ----------------------------------------------------
__device__ __forceinline__ uint32_t f2tf(float f) {
    uint32_t u;
    asm("cvt.rna.tf32.f32 %0, %1;" : "=r"(u) : "f"(f));
    return u;
}

__device__ __forceinline__ void mma_tf32(float c[4], const uint32_t a[4], const uint32_t b[2]) {
    asm volatile(
        "mma.sync.aligned.m16n8k8.row.col.f32.tf32.tf32.f32 "
        "{%0,%1,%2,%3},{%4,%5,%6,%7},{%8,%9},{%0,%1,%2,%3};\n"
        : "+f"(c[0]), "+f"(c[1]), "+f"(c[2]), "+f"(c[3])
        : "r"(a[0]), "r"(a[1]), "r"(a[2]), "r"(a[3]),
          "r"(b[0]), "r"(b[1]));
}

// ---------------- fused per-token indexed LayerNorm ---------------------------
__global__ void ln_kernel(const float* __restrict__ x, const int* __restrict__ ts,
                          const float* __restrict__ gamma, const float* __restrict__ beta,
                          const float* __restrict__ decay, int T, float* __restrict__ out) {
    __shared__ float s1[8], s2[8];
    long row = blockIdx.x;
    int tid = threadIdx.x;                          // 256 threads, float4 each = 1024
    float4 v = reinterpret_cast<const float4*>(x + row * DD)[tid];
    float s = v.x + v.y + v.z + v.w;
    float q = v.x * v.x + v.y * v.y + v.z * v.z + v.w * v.w;
    #pragma unroll
    for (int o = 16; o; o >>= 1) {
        s += __shfl_xor_sync(0xffffffffu, s, o);
        q += __shfl_xor_sync(0xffffffffu, q, o);
    }
    if ((tid & 31) == 0) { s1[tid >> 5] = s; s2[tid >> 5] = q; }
    __syncthreads();
    float Sm = 0.f, Qm = 0.f;
    #pragma unroll
    for (int i = 0; i < 8; i++) { Sm += s1[i]; Qm += s2[i]; }
    float mu   = Sm * (1.0f / DD);
    float var  = Qm * (1.0f / DD) - mu * mu;
    float rstd = rsqrtf(var + 1e-5f);

    int tv = ts[row];
    float4 o;
    if (tv < T) {
        int idx = tv < 0 ? 0 : tv;                  // clip(t, 0, T-1); tv<T already
        float4 gm = reinterpret_cast<const float4*>(gamma + (long)idx * DD)[tid];
        float4 bt = reinterpret_cast<const float4*>(beta  + (long)idx * DD)[tid];
        float dk = decay[idx];
        o.x = ((v.x - mu) * rstd * gm.x + bt.x) * dk;
        o.y = ((v.y - mu) * rstd * gm.y + bt.y) * dk;
        o.z = ((v.z - mu) * rstd * gm.z + bt.z) * dk;
        o.w = ((v.w - mu) * rstd * gm.w + bt.w) * dk;
    } else {
        o = v;
    }
    reinterpret_cast<float4*>(out + row * DD)[tid] = o;
}

// ---------------- row softmax (rows of 2048) ----------------------------------
__global__ void softmax_kernel(float* __restrict__ sc) {
    __shared__ float red[8];
    long row = (long)blockIdx.y * gridDim.x + blockIdx.x;
    float* r = sc + row * SS;
    int tid = threadIdx.x;                          // 256 threads * 8 = 2048
    float4 a = reinterpret_cast<float4*>(r)[tid];
    float4 b = reinterpret_cast<float4*>(r)[tid + 256];
    float mx = fmaxf(fmaxf(fmaxf(a.x, a.y), fmaxf(a.z, a.w)),
                     fmaxf(fmaxf(b.x, b.y), fmaxf(b.z, b.w)));
    #pragma unroll
    for (int o = 16; o; o >>= 1) mx = fmaxf(mx, __shfl_xor_sync(0xffffffffu, mx, o));
    if ((tid & 31) == 0) red[tid >> 5] = mx;
    __syncthreads();
    float m = red[0];
    #pragma unroll
    for (int i = 1; i < 8; i++) m = fmaxf(m, red[i]);
    __syncthreads();

    a.x = __expf(a.x - m); a.y = __expf(a.y - m); a.z = __expf(a.z - m); a.w = __expf(a.w - m);
    b.x = __expf(b.x - m); b.y = __expf(b.y - m); b.z = __expf(b.z - m); b.w = __expf(b.w - m);
    float s = a.x + a.y + a.z + a.w + b.x + b.y + b.z + b.w;
    #pragma unroll
    for (int o = 16; o; o >>= 1) s += __shfl_xor_sync(0xffffffffu, s, o);
    if ((tid & 31) == 0) red[tid >> 5] = s;
    __syncthreads();
    float tot = 0.f;
    #pragma unroll
    for (int i = 0; i < 8; i++) tot += red[i];
    float inv = 1.0f / tot;
    a.x *= inv; a.y *= inv; a.z *= inv; a.w *= inv;
    b.x *= inv; b.y *= inv; b.z *= inv; b.w *= inv;
    reinterpret_cast<float4*>(r)[tid]       = a;
    reinterpret_cast<float4*>(r)[tid + 256] = b;
}

// ---------------- generic tf32 GEMM ------------------------------------------
// C[m,n] = alpha * sum_k A[m,k] * B'[k,n]  (+ bias[n]) (+ Res[m,n])
//   TRANSB=true : B is [N,K] row-major (B' = B^T)   -- "NT"
//   TRANSB=false: B is [K,N] row-major              -- "NN"
// Batched over blockIdx.z: z -> (bb = z/Hh, hh = z%Hh) pointer offsets.
#define BM 128
#define BN 128
#define BK 32
#define LDSH 36   // padded smem K-stride (conflict-free: 36%32==4)

template<bool TRANSB>
__global__ __launch_bounds__(256, 2)
void gemm_tf32(const float* __restrict__ A, int lda, long sAb, long sAh,
               const float* __restrict__ B, int ldb, long sBb, long sBh,
               float* __restrict__ C, int ldc, long sCb, long sCh,
               const float* __restrict__ bias,
               const float* __restrict__ Res, int ldres, long sRb, long sRh,
               float alpha, int K, int Hh) {
    __shared__ uint32_t As[BM][LDSH];
    __shared__ uint32_t Bs[BN][LDSH];

    int z = blockIdx.z;
    int bb = z / Hh, hh = z % Hh;
    A += bb * sAb + hh * sAh;
    B += bb * sBb + hh * sBh;
    C += bb * sCb + hh * sCh;
    if (Res) Res += bb * sRb + hh * sRh;

    const int m0 = blockIdx.y * BM;
    const int n0 = blockIdx.x * BN;

    const int tid  = threadIdx.x;
    const int warp = tid >> 5, lane = tid & 31;
    const int g = lane >> 2, t = lane & 3;
    const int wm = (warp >> 2) * 64;   // warp m-origin (2 warps in m)
    const int wn = (warp & 3) * 32;    // warp n-origin (4 warps in n)

    float c[4][4][4];
    #pragma unroll
    for (int i = 0; i < 4; i++)
        #pragma unroll
        for (int j = 0; j < 4; j++)
            #pragma unroll
            for (int r = 0; r < 4; r++) c[i][j][r] = 0.f;

    for (int k0 = 0; k0 < K; k0 += BK) {
        // ---- A tile: BM x BK, coalesced float4 along K ----
        #pragma unroll
        for (int it = 0; it < 4; it++) {
            int idx = tid + it * 256;          // 0..1023
            int r  = idx >> 3;                 // 0..127
            int cc = (idx & 7) << 2;           // 0,4,..,28
            float4 v = *reinterpret_cast<const float4*>(&A[(long)(m0 + r) * lda + k0 + cc]);
            uint4 u;
            u.x = f2tf(v.x); u.y = f2tf(v.y); u.z = f2tf(v.z); u.w = f2tf(v.w);
            *reinterpret_cast<uint4*>(&As[r][cc]) = u;
        }
        // ---- B tile ----
        if (TRANSB) {
            #pragma unroll
            for (int it = 0; it < 4; it++) {
                int idx = tid + it * 256;
                int r  = idx >> 3;
                int cc = (idx & 7) << 2;
                float4 v = *reinterpret_cast<const float4*>(&B[(long)(n0 + r) * ldb + k0 + cc]);
                uint4 u;
                u.x = f2tf(v.x); u.y = f2tf(v.y); u.z = f2tf(v.z); u.w = f2tf(v.w);
                *reinterpret_cast<uint4*>(&Bs[r][cc]) = u;
            }
        } else {
            #pragma unroll
            for (int it = 0; it < 4; it++) {
                int idx = tid + it * 256;
                int kr = idx >> 5;                 // 0..31
                int nc = (idx & 31) << 2;          // 0..124
                float4 v = *reinterpret_cast<const float4*>(&B[(long)(k0 + kr) * ldb + n0 + nc]);
                Bs[nc + 0][kr] = f2tf(v.x);
                Bs[nc + 1][kr] = f2tf(v.y);
                Bs[nc + 2][kr] = f2tf(v.z);
                Bs[nc + 3][kr] = f2tf(v.w);
            }
        }
        __syncthreads();

        #pragma unroll
        for (int kk = 0; kk < BK; kk += 8) {
            uint32_t a[4][4], b[4][2];
            #pragma unroll
            for (int mi = 0; mi < 4; mi++) {
                int rb = wm + mi * 16;
                a[mi][0] = As[rb + g    ][kk + t];
                a[mi][1] = As[rb + g + 8][kk + t];
                a[mi][2] = As[rb + g    ][kk + t + 4];
                a[mi][3] = As[rb + g + 8][kk + t + 4];
            }
            #pragma unroll
            for (int ni = 0; ni < 4; ni++) {
                int nb = wn + ni * 8 + g;
                b[ni][0] = Bs[nb][kk + t];
                b[ni][1] = Bs[nb][kk + t + 4];
            }
            #pragma unroll
            for (int mi = 0; mi < 4; mi++)
                #pragma unroll
                for (int ni = 0; ni < 4; ni++)
                    mma_tf32(c[mi][ni], a[mi], b[ni]);
        }
        __syncthreads();
    }

    // ---- epilogue ----
    #pragma unroll
    for (int mi = 0; mi < 4; mi++) {
        #pragma unroll
        for (int ni = 0; ni < 4; ni++) {
            int row0 = m0 + wm + mi * 16 + g;
            int col  = n0 + wn + ni * 8 + 2 * t;
            float2 v0, v1;
            v0.x = c[mi][ni][0] * alpha; v0.y = c[mi][ni][1] * alpha;
            v1.x = c[mi][ni][2] * alpha; v1.y = c[mi][ni][3] * alpha;
            if (bias) {
                float b0 = bias[col], b1 = bias[col + 1];
                v0.x += b0; v0.y += b1; v1.x += b0; v1.y += b1;
            }
            if (Res) {
                v0.x += Res[(long)row0 * ldres + col];
                v0.y += Res[(long)row0 * ldres + col + 1];
                v1.x += Res[(long)(row0 + 8) * ldres + col];
                v1.y += Res[(long)(row0 + 8) * ldres + col + 1];
            }
            *reinterpret_cast<float2*>(&C[(long)row0 * ldc + col])       = v0;
            *reinterpret_cast<float2*>(&C[(long)(row0 + 8) * ldc + col]) = v1;
        }
    }
}

// ---------------- launch ------------------------------------------------------
extern "C" void kernel_launch(void* const* d_in, const int* in_sizes, int n_in,
                              void* d_out, int out_size) {
    const float* x      = (const float*)d_in[0];
    const int*   ts     = (const int*)  d_in[1];
    const float* gamma  = (const float*)d_in[2];
    const float* beta   = (const float*)d_in[3];
    const float* decay  = (const float*)d_in[4];
    const float* shiftW = (const float*)d_in[5];
    const float* shiftb = (const float*)d_in[6];
    const float* inW    = (const float*)d_in[7];
    const float* inb    = (const float*)d_in[8];
    const float* outW   = (const float*)d_in[9];
    const float* outb   = (const float*)d_in[10];
    float* out = (float*)d_out;

    const int T  = in_sizes[4];            // decay length
    const int BS = in_sizes[0] / DD;       // B*S = 8192
    const int Bb = BS / SS;                // 4

    float *XLN, *X2, *QKV, *SC, *CTX;
    cudaGetSymbolAddress((void**)&XLN, g_XLN);
    cudaGetSymbolAddress((void**)&X2,  g_X2);
    cudaGetSymbolAddress((void**)&QKV, g_QKV);
    cudaGetSymbolAddress((void**)&SC,  g_SC);
    cudaGetSymbolAddress((void**)&CTX, g_CTX);

    // 1) indexed LayerNorm
    ln_kernel<<<BS, 256>>>(x, ts, gamma, beta, decay, T, XLN);

    // 2) X2 = XLN + XLN @ shiftW^T + shiftb
    gemm_tf32<true><<<dim3(DD / BN, BS / BM, 1), 256>>>(
        XLN, DD, 0, 0,  shiftW, DD, 0, 0,  X2, DD, 0, 0,
        shiftb,  XLN, DD, 0, 0,  1.0f, DD, 1);

    // 3) QKV = X2 @ inW^T + inb
    gemm_tf32<true><<<dim3(3 * DD / BN, BS / BM, 1), 256>>>(
        X2, DD, 0, 0,  inW, DD, 0, 0,  QKV, 3 * DD, 0, 0,
        inb,  nullptr, 0, 0, 0,  1.0f, DD, 1);

    // 4) attention, chunked over batch (scores scratch = one batch of 8 heads)
    const long sTok = (long)SS * 3 * DD;    // per-batch stride in QKV
    const float scale = 1.0f / sqrtf((float)HDIM);
    for (int b = 0; b < Bb; b++) {
        const float* Qp = QKV + (long)b * sTok;
        const float* Kp = QKV + (long)b * sTok + DD;
        const float* Vp = QKV + (long)b * sTok + 2 * DD;
        float* Cp = CTX + (long)b * SS * DD;

        // scores[h] = scale * Q_h @ K_h^T     (M=S, N=S, K=128)
        gemm_tf32<true><<<dim3(SS / BN, SS / BM, NH), 256>>>(
            Qp, 3 * DD, 0, HDIM,  Kp, 3 * DD, 0, HDIM,
            SC, SS, 0, (long)SS * SS,
            nullptr,  nullptr, 0, 0, 0,  scale, HDIM, NH);

        // row softmax
        softmax_kernel<<<dim3(SS, NH), 256>>>(SC);

        // ctx[h] = P_h @ V_h                  (M=S, N=128, K=S), NN
        gemm_tf32<false><<<dim3(HDIM / BN, SS / BM, NH), 256>>>(
            SC, SS, 0, (long)SS * SS,  Vp, 3 * DD, 0, HDIM,
            Cp, DD, 0, HDIM,
            nullptr,  nullptr, 0, 0, 0,  1.0f, SS, NH);
    }

    // 5) out = X2 + CTX @ outW^T + outb
    gemm_tf32<true><<<dim3(DD / BN, BS / BM, 1), 256>>>(
        CTX, DD, 0, 0,  outW, DD, 0, 0,  out, DD, 0, 0,
        outb,  X2, DD, 0, 0,  1.0f, DD, 1);
}

// round 2
// speedup vs baseline: 2.4778x; 2.4778x over previous
#include <cuda_runtime.h>
#include <cuda_fp16.h>
#include <cstdint>
#include <math.h>

#define DD   1024
#define SS   2048
#define NH   8
#define HDIM 128
#define BB   4

// ---------------- scratch (static device globals; no allocation) -------------
__device__ float  g_XLN32[8192 * 1024];
__device__ float  g_X232 [8192 * 1024];
__device__ __half g_XLN16[8192 * 1024];
__device__ __half g_X216 [8192 * 1024];
__device__ __half g_QKV16[(size_t)8192 * 3072];
__device__ __half g_SC16 [(size_t)BB * NH * SS * SS];   // 256 MB fp16 scores
__device__ __half g_CTX16[8192 * 1024];
__device__ __half g_W16  [(size_t)5 * 1024 * 1024];     // shiftW | inW | outW (fp16)

// ---------------- ptx helpers --------------------------------------------------
__device__ __forceinline__ uint32_t sptr(const void* p) {
    return (uint32_t)__cvta_generic_to_shared(p);
}
__device__ __forceinline__ void cp16(uint32_t s, const void* g) {
    asm volatile("cp.async.cg.shared.global [%0], [%1], 16;\n" :: "r"(s), "l"(g));
}
__device__ __forceinline__ void cp_commit() {
    asm volatile("cp.async.commit_group;\n");
}
__device__ __forceinline__ void ldsm_x4(uint32_t* r, uint32_t a) {
    asm volatile("ldmatrix.sync.aligned.m8n8.x4.shared.b16 {%0,%1,%2,%3}, [%4];\n"
                 : "=r"(r[0]), "=r"(r[1]), "=r"(r[2]), "=r"(r[3]) : "r"(a));
}
__device__ __forceinline__ void ldsm_x4_t(uint32_t* r, uint32_t a) {
    asm volatile("ldmatrix.sync.aligned.m8n8.x4.trans.shared.b16 {%0,%1,%2,%3}, [%4];\n"
                 : "=r"(r[0]), "=r"(r[1]), "=r"(r[2]), "=r"(r[3]) : "r"(a));
}
__device__ __forceinline__ void mma16816(float c[4], const uint32_t a[4], const uint32_t b[2]) {
    asm volatile(
        "mma.sync.aligned.m16n8k16.row.col.f32.f16.f16.f32 "
        "{%0,%1,%2,%3},{%4,%5,%6,%7},{%8,%9},{%0,%1,%2,%3};\n"
        : "+f"(c[0]), "+f"(c[1]), "+f"(c[2]), "+f"(c[3])
        : "r"(a[0]), "r"(a[1]), "r"(a[2]), "r"(a[3]), "r"(b[0]), "r"(b[1]));
}

// ---------------- f32 -> f16 convert ------------------------------------------
__global__ void f2h_kernel(const float* __restrict__ a, __half* __restrict__ o, int n4) {
    int i = blockIdx.x * 256 + threadIdx.x;
    if (i < n4) {
        float4 v = reinterpret_cast<const float4*>(a)[i];
        __half2* p = reinterpret_cast<__half2*>(o) + i * 2;
        p[0] = __floats2half2_rn(v.x, v.y);
        p[1] = __floats2half2_rn(v.z, v.w);
    }
}

// ---------------- fused per-token indexed LayerNorm ----------------------------
__global__ void ln_kernel(const float* __restrict__ x, const int* __restrict__ ts,
                          const float* __restrict__ gamma, const float* __restrict__ beta,
                          const float* __restrict__ decay, int T,
                          float* __restrict__ o32, __half* __restrict__ o16) {
    __shared__ float s1[8], s2[8];
    long row = blockIdx.x;
    int tid = threadIdx.x;                          // 256 threads, float4 each = 1024
    float4 v = reinterpret_cast<const float4*>(x + row * DD)[tid];
    float s = v.x + v.y + v.z + v.w;
    float q = v.x * v.x + v.y * v.y + v.z * v.z + v.w * v.w;
    #pragma unroll
    for (int o = 16; o; o >>= 1) {
        s += __shfl_xor_sync(0xffffffffu, s, o);
        q += __shfl_xor_sync(0xffffffffu, q, o);
    }
    if ((tid & 31) == 0) { s1[tid >> 5] = s; s2[tid >> 5] = q; }
    __syncthreads();
    float Sm = 0.f, Qm = 0.f;
    #pragma unroll
    for (int i = 0; i < 8; i++) { Sm += s1[i]; Qm += s2[i]; }
    float mu   = Sm * (1.0f / DD);
    float var  = Qm * (1.0f / DD) - mu * mu;
    float rstd = rsqrtf(var + 1e-5f);

    int tv = ts[row];
    float4 o;
    if (tv < T) {
        int idx = tv < 0 ? 0 : tv;
        float4 gm = reinterpret_cast<const float4*>(gamma + (long)idx * DD)[tid];
        float4 bt = reinterpret_cast<const float4*>(beta  + (long)idx * DD)[tid];
        float dk = decay[idx];
        o.x = ((v.x - mu) * rstd * gm.x + bt.x) * dk;
        o.y = ((v.y - mu) * rstd * gm.y + bt.y) * dk;
        o.z = ((v.z - mu) * rstd * gm.z + bt.z) * dk;
        o.w = ((v.w - mu) * rstd * gm.w + bt.w) * dk;
    } else {
        o = v;
    }
    reinterpret_cast<float4*>(o32 + row * DD)[tid] = o;
    __half2* p = reinterpret_cast<__half2*>(o16 + row * DD) + tid * 2;
    p[0] = __floats2half2_rn(o.x, o.y);
    p[1] = __floats2half2_rn(o.z, o.w);
}

// ---------------- fp16 row softmax (rows of 2048) -------------------------------
__global__ void softmax_h(__half* __restrict__ sc) {
    __shared__ float red[8];
    long row = blockIdx.x;
    __half* r = sc + row * SS;
    int tid = threadIdx.x;                          // 256 threads * 8 halves = 2048
    uint4 u = reinterpret_cast<uint4*>(r)[tid];
    __half2 h0 = *reinterpret_cast<__half2*>(&u.x);
    __half2 h1 = *reinterpret_cast<__half2*>(&u.y);
    __half2 h2 = *reinterpret_cast<__half2*>(&u.z);
    __half2 h3 = *reinterpret_cast<__half2*>(&u.w);
    float f[8];
    f[0] = __low2float(h0); f[1] = __high2float(h0);
    f[2] = __low2float(h1); f[3] = __high2float(h1);
    f[4] = __low2float(h2); f[5] = __high2float(h2);
    f[6] = __low2float(h3); f[7] = __high2float(h3);
    float mx = f[0];
    #pragma unroll
    for (int i = 1; i < 8; i++) mx = fmaxf(mx, f[i]);
    #pragma unroll
    for (int o = 16; o; o >>= 1) mx = fmaxf(mx, __shfl_xor_sync(0xffffffffu, mx, o));
    if ((tid & 31) == 0) red[tid >> 5] = mx;
    __syncthreads();
    float m = red[0];
    #pragma unroll
    for (int i = 1; i < 8; i++) m = fmaxf(m, red[i]);
    __syncthreads();
    float s = 0.f;
    #pragma unroll
    for (int i = 0; i < 8; i++) { f[i] = __expf(f[i] - m); s += f[i]; }
    #pragma unroll
    for (int o = 16; o; o >>= 1) s += __shfl_xor_sync(0xffffffffu, s, o);
    if ((tid & 31) == 0) red[tid >> 5] = s;
    __syncthreads();
    float tot = 0.f;
    #pragma unroll
    for (int i = 0; i < 8; i++) tot += red[i];
    float inv = 1.0f / tot;
    #pragma unroll
    for (int i = 0; i < 8; i++) f[i] *= inv;
    h0 = __floats2half2_rn(f[0], f[1]);
    h1 = __floats2half2_rn(f[2], f[3]);
    h2 = __floats2half2_rn(f[4], f[5]);
    h3 = __floats2half2_rn(f[6], f[7]);
    u.x = *reinterpret_cast<uint32_t*>(&h0);
    u.y = *reinterpret_cast<uint32_t*>(&h1);
    u.z = *reinterpret_cast<uint32_t*>(&h2);
    u.w = *reinterpret_cast<uint32_t*>(&h3);
    reinterpret_cast<uint4*>(r)[tid] = u;
}

// ---------------- fp16 GEMM (ldmatrix + mma.m16n8k16 + cp.async pipeline) -------
// C[m,n] = alpha * sum_k A[m,k] * B'[k,n] (+ bias[n]) (+ Res[m,n])
//   TRANSB=true : B is [N,K] row-major (B' = B^T)   -- "NT"
//   TRANSB=false: B is [K,N] row-major              -- "NN"
#define BM 128
#define BN 128
#define BK 32
#define ALD 40    // A/B(NT) smem row stride (halves): 80B -> conflict-free ldmatrix
#define BLD 136   // B(NN) smem row stride (halves): 272B -> conflict-free ldmatrix

template<bool TRANSB>
__global__ __launch_bounds__(256, 2)
void hgemm(const __half* __restrict__ A, int lda, long sAb, long sAh,
           const __half* __restrict__ B, int ldb, long sBb, long sBh,
           int ldc, long sCb, long sCh,
           float* __restrict__ C32, __half* __restrict__ C16,
           const float* __restrict__ bias,
           const float* __restrict__ Res, int ldres,
           float alpha, int K, int Hh)
{
    __shared__ alignas(16) __half As[2][BM * ALD];
    __shared__ alignas(16) __half Bs[2][BM * ALD];   // NN uses 32*136 <= 128*40

    const int z = blockIdx.z;
    const int bb = z / Hh, hh = z % Hh;
    A += bb * sAb + hh * sAh;
    B += bb * sBb + hh * sBh;
    const long coff = bb * sCb + hh * sCh;
    if (C32) C32 += coff;
    if (C16) C16 += coff;

    const int m0 = blockIdx.y * BM;
    const int n0 = blockIdx.x * BN;

    const int tid  = threadIdx.x;
    const int warp = tid >> 5, lane = tid & 31;
    const int g = lane >> 2, t = lane & 3;
    const int wm = (warp >> 2) * 64;   // 2 warps in m
    const int wn = (warp & 3) * 32;    // 4 warps in n

    float c[4][4][4];
    #pragma unroll
    for (int i = 0; i < 4; i++)
        #pragma unroll
        for (int j = 0; j < 4; j++)
            #pragma unroll
            for (int r = 0; r < 4; r++) c[i][j][r] = 0.f;

    // ---- async tile loaders (16B per cp.async) ----
    auto loadA = [&](int st, int k0) {
        #pragma unroll
        for (int i = 0; i < 2; i++) {
            int ch = tid + i * 256;            // 512 chunks: 128 rows x 4
            int r = ch >> 2, o = (ch & 3) * 8;
            cp16(sptr(&As[st][r * ALD + o]), A + (long)(m0 + r) * lda + k0 + o);
        }
    };
    auto loadB = [&](int st, int k0) {
        if (TRANSB) {
            #pragma unroll
            for (int i = 0; i < 2; i++) {
                int ch = tid + i * 256;        // 512 chunks: 128 n-rows x 4
                int r = ch >> 2, o = (ch & 3) * 8;
                cp16(sptr(&Bs[st][r * ALD + o]), B + (long)(n0 + r) * ldb + k0 + o);
            }
        } else {
            #pragma unroll
            for (int i = 0; i < 2; i++) {
                int ch = tid + i * 256;        // 512 chunks: 32 k-rows x 16
                int r = ch >> 4, o = (ch & 15) * 8;
                cp16(sptr(&Bs[st][r * BLD + o]), B + (long)(k0 + r) * ldb + n0 + o);
            }
        }
    };

    auto compute = [&](int st) {
        #pragma unroll
        for (int kk = 0; kk < BK; kk += 16) {
            uint32_t a[4][4];
            #pragma unroll
            for (int mi = 0; mi < 4; mi++)
                ldsm_x4(a[mi], sptr(&As[st][(wm + mi * 16 + (lane & 15)) * ALD
                                            + kk + (lane >> 4) * 8]));
            uint32_t b[2][4];
            if (TRANSB) {
                #pragma unroll
                for (int nt = 0; nt < 2; nt++)
                    ldsm_x4(b[nt], sptr(&Bs[st][(wn + nt * 16 + (lane & 7) + ((lane >> 4) << 3)) * ALD
                                                + kk + ((lane >> 3) & 1) * 8]));
            } else {
                #pragma unroll
                for (int nt = 0; nt < 2; nt++)
                    ldsm_x4_t(b[nt], sptr(&Bs[st][(kk + (lane & 15)) * BLD
                                                  + wn + nt * 16 + (lane >> 4) * 8]));
            }
            #pragma unroll
            for (int mi = 0; mi < 4; mi++)
                #pragma unroll
                for (int ni = 0; ni < 4; ni++)
                    mma16816(c[mi][ni], a[mi], &b[ni >> 1][(ni & 1) * 2]);
        }
    };

    // ---- 2-stage pipeline ----
    const int KT = K / BK;
    loadA(0, 0); loadB(0, 0); cp_commit();
    int st = 0;
    for (int kt = 0; kt < KT; kt++) {
        if (kt + 1 < KT) {
            loadA(st ^ 1, (kt + 1) * BK); loadB(st ^ 1, (kt + 1) * BK); cp_commit();
            asm volatile("cp.async.wait_group 1;\n");
        } else {
            asm volatile("cp.async.wait_group 0;\n");
        }
        __syncthreads();
        compute(st);
        __syncthreads();
        st ^= 1;
    }

    // ---- epilogue ----
    #pragma unroll
    for (int mi = 0; mi < 4; mi++) {
        #pragma unroll
        for (int ni = 0; ni < 4; ni++) {
            int row0 = m0 + wm + mi * 16 + g;
            int col  = n0 + wn + ni * 8 + 2 * t;
            float2 v0, v1;
            v0.x = c[mi][ni][0] * alpha; v0.y = c[mi][ni][1] * alpha;
            v1.x = c[mi][ni][2] * alpha; v1.y = c[mi][ni][3] * alpha;
            if (bias) {
                float b0 = bias[col], b1 = bias[col + 1];
                v0.x += b0; v0.y += b1; v1.x += b0; v1.y += b1;
            }
            if (Res) {
                v0.x += Res[(long)row0 * ldres + col];
                v0.y += Res[(long)row0 * ldres + col + 1];
                v1.x += Res[(long)(row0 + 8) * ldres + col];
                v1.y += Res[(long)(row0 + 8) * ldres + col + 1];
            }
            if (C32) {
                *reinterpret_cast<float2*>(&C32[(long)row0 * ldc + col])       = v0;
                *reinterpret_cast<float2*>(&C32[(long)(row0 + 8) * ldc + col]) = v1;
            }
            if (C16) {
                *reinterpret_cast<__half2*>(&C16[(long)row0 * ldc + col])       = __floats2half2_rn(v0.x, v0.y);
                *reinterpret_cast<__half2*>(&C16[(long)(row0 + 8) * ldc + col]) = __floats2half2_rn(v1.x, v1.y);
            }
        }
    }
}

// ---------------- launch --------------------------------------------------------
extern "C" void kernel_launch(void* const* d_in, const int* in_sizes, int n_in,
                              void* d_out, int out_size) {
    const float* x      = (const float*)d_in[0];
    const int*   ts     = (const int*)  d_in[1];
    const float* gamma  = (const float*)d_in[2];
    const float* beta   = (const float*)d_in[3];
    const float* decay  = (const float*)d_in[4];
    const float* shiftW = (const float*)d_in[5];
    const float* shiftb = (const float*)d_in[6];
    const float* inW    = (const float*)d_in[7];
    const float* inb    = (const float*)d_in[8];
    const float* outW   = (const float*)d_in[9];
    const float* outb   = (const float*)d_in[10];
    float* out = (float*)d_out;

    const int T  = in_sizes[4];
    const int BS = in_sizes[0] / DD;       // 8192

    float *XLN32, *X232;
    __half *XLN16, *X216, *QKV16, *SC16, *CTX16, *W16;
    cudaGetSymbolAddress((void**)&XLN32, g_XLN32);
    cudaGetSymbolAddress((void**)&X232,  g_X232);
    cudaGetSymbolAddress((void**)&XLN16, g_XLN16);
    cudaGetSymbolAddress((void**)&X216,  g_X216);
    cudaGetSymbolAddress((void**)&QKV16, g_QKV16);
    cudaGetSymbolAddress((void**)&SC16,  g_SC16);
    cudaGetSymbolAddress((void**)&CTX16, g_CTX16);
    cudaGetSymbolAddress((void**)&W16,   g_W16);

    __half* shW16 = W16;
    __half* inW16 = W16 + (size_t)1024 * 1024;
    __half* otW16 = W16 + (size_t)4 * 1024 * 1024;

    // 0) convert weights to fp16
    f2h_kernel<<<(1024 * 1024 / 4 + 255) / 256, 256>>>(shiftW, shW16, 1024 * 1024 / 4);
    f2h_kernel<<<(3072 * 1024 / 4 + 255) / 256, 256>>>(inW,    inW16, 3072 * 1024 / 4);
    f2h_kernel<<<(1024 * 1024 / 4 + 255) / 256, 256>>>(outW,   otW16, 1024 * 1024 / 4);

    // 1) indexed LayerNorm -> XLN32 + XLN16
    ln_kernel<<<BS, 256>>>(x, ts, gamma, beta, decay, T, XLN32, XLN16);

    // 2) X2 = XLN + XLN @ shiftW^T + shiftb   (writes f32 + f16)
    hgemm<true><<<dim3(DD / BN, BS / BM, 1), 256>>>(
        XLN16, DD, 0, 0,  shW16, DD, 0, 0,
        DD, 0, 0,  X232, X216,  shiftb,  XLN32, DD,  1.0f, DD, 1);

    // 3) QKV = X2 @ inW^T + inb   (f16 only)
    hgemm<true><<<dim3(3 * DD / BN, BS / BM, 1), 256>>>(
        X216, DD, 0, 0,  inW16, DD, 0, 0,
        3 * DD, 0, 0,  nullptr, QKV16,  inb,  nullptr, 0,  1.0f, DD, 1);

    // 4a) scores = scale * Q @ K^T   (all batches/heads, z = 32)
    const long sTok = (long)SS * 3 * DD;
    hgemm<true><<<dim3(SS / BN, SS / BM, BB * NH), 256>>>(
        QKV16,          3 * DD, sTok, HDIM,
        QKV16 + DD,     3 * DD, sTok, HDIM,
        SS, (long)NH * SS * SS, (long)SS * SS,
        nullptr, SC16,  nullptr,  nullptr, 0,
        0.08838834764831845f, HDIM, NH);

    // 4b) softmax (fp16 in/out)
    softmax_h<<<BB * NH * SS, 256>>>(SC16);

    // 4c) ctx = P @ V   (NN)
    hgemm<false><<<dim3(HDIM / BN, SS / BM, BB * NH), 256>>>(
        SC16,           SS, (long)NH * SS * SS, (long)SS * SS,
        QKV16 + 2 * DD, 3 * DD, sTok, HDIM,
        DD, (long)SS * DD, HDIM,
        nullptr, CTX16,  nullptr,  nullptr, 0,
        1.0f, SS, NH);

    // 5) out = X2 + CTX @ outW^T + outb   (f32)
    hgemm<true><<<dim3(DD / BN, BS / BM, 1), 256>>>(
        CTX16, DD, 0, 0,  otW16, DD, 0, 0,
        DD, 0, 0,  out, nullptr,  outb,  X232, DD,  1.0f, DD, 1);
}

// round 3
// speedup vs baseline: 3.1510x; 1.2717x over previous
#include <cuda_runtime.h>
#include <cuda_fp16.h>
#include <cstdint>
#include <math.h>

#define DD   1024
#define SS   2048
#define NH   8
#define HDIM 128
#define BB   4

// ---------------- scratch (static device globals; no allocation) -------------
__device__ float  g_XLN32[8192 * 1024];
__device__ float  g_X232 [8192 * 1024];
__device__ __half g_XLN16[8192 * 1024];
__device__ __half g_X216 [8192 * 1024];
__device__ __half g_QKV16[(size_t)8192 * 3072];
__device__ __half g_CTX16[8192 * 1024];
__device__ __half g_W16  [(size_t)5 * 1024 * 1024];     // shiftW | inW | outW (fp16)

// ---------------- ptx helpers --------------------------------------------------
__device__ __forceinline__ uint32_t sptr(const void* p) {
    return (uint32_t)__cvta_generic_to_shared(p);
}
__device__ __forceinline__ void cp16(uint32_t s, const void* g) {
    asm volatile("cp.async.cg.shared.global [%0], [%1], 16;\n" :: "r"(s), "l"(g));
}
__device__ __forceinline__ void cp_commit() {
    asm volatile("cp.async.commit_group;\n");
}
__device__ __forceinline__ void ldsm_x4(uint32_t* r, uint32_t a) {
    asm volatile("ldmatrix.sync.aligned.m8n8.x4.shared.b16 {%0,%1,%2,%3}, [%4];\n"
                 : "=r"(r[0]), "=r"(r[1]), "=r"(r[2]), "=r"(r[3]) : "r"(a));
}
__device__ __forceinline__ void ldsm_x4_t(uint32_t* r, uint32_t a) {
    asm volatile("ldmatrix.sync.aligned.m8n8.x4.trans.shared.b16 {%0,%1,%2,%3}, [%4];\n"
                 : "=r"(r[0]), "=r"(r[1]), "=r"(r[2]), "=r"(r[3]) : "r"(a));
}
__device__ __forceinline__ void mma16816(float c[4], const uint32_t a[4], const uint32_t b[2]) {
    asm volatile(
        "mma.sync.aligned.m16n8k16.row.col.f32.f16.f16.f32 "
        "{%0,%1,%2,%3},{%4,%5,%6,%7},{%8,%9},{%0,%1,%2,%3};\n"
        : "+f"(c[0]), "+f"(c[1]), "+f"(c[2]), "+f"(c[3])
        : "r"(a[0]), "r"(a[1]), "r"(a[2]), "r"(a[3]), "r"(b[0]), "r"(b[1]));
}
__device__ __forceinline__ uint32_t packh2(float a, float b) {
    __half2 h = __floats2half2_rn(a, b);
    return *reinterpret_cast<uint32_t*>(&h);
}

// ---------------- f32 -> f16 convert ------------------------------------------
__global__ void f2h_kernel(const float* __restrict__ a, __half* __restrict__ o, int n4) {
    int i = blockIdx.x * 256 + threadIdx.x;
    if (i < n4) {
        float4 v = reinterpret_cast<const float4*>(a)[i];
        __half2* p = reinterpret_cast<__half2*>(o) + i * 2;
        p[0] = __floats2half2_rn(v.x, v.y);
        p[1] = __floats2half2_rn(v.z, v.w);
    }
}

// ---------------- fused per-token indexed LayerNorm ----------------------------
__global__ void ln_kernel(const float* __restrict__ x, const int* __restrict__ ts,
                          const float* __restrict__ gamma, const float* __restrict__ beta,
                          const float* __restrict__ decay, int T,
                          float* __restrict__ o32, __half* __restrict__ o16) {
    __shared__ float s1[8], s2[8];
    long row = blockIdx.x;
    int tid = threadIdx.x;
    float4 v = reinterpret_cast<const float4*>(x + row * DD)[tid];
    float s = v.x + v.y + v.z + v.w;
    float q = v.x * v.x + v.y * v.y + v.z * v.z + v.w * v.w;
    #pragma unroll
    for (int o = 16; o; o >>= 1) {
        s += __shfl_xor_sync(0xffffffffu, s, o);
        q += __shfl_xor_sync(0xffffffffu, q, o);
    }
    if ((tid & 31) == 0) { s1[tid >> 5] = s; s2[tid >> 5] = q; }
    __syncthreads();
    float Sm = 0.f, Qm = 0.f;
    #pragma unroll
    for (int i = 0; i < 8; i++) { Sm += s1[i]; Qm += s2[i]; }
    float mu   = Sm * (1.0f / DD);
    float var  = Qm * (1.0f / DD) - mu * mu;
    float rstd = rsqrtf(var + 1e-5f);

    int tv = ts[row];
    float4 o;
    if (tv < T) {
        int idx = tv < 0 ? 0 : tv;
        float4 gm = reinterpret_cast<const float4*>(gamma + (long)idx * DD)[tid];
        float4 bt = reinterpret_cast<const float4*>(beta  + (long)idx * DD)[tid];
        float dk = decay[idx];
        o.x = ((v.x - mu) * rstd * gm.x + bt.x) * dk;
        o.y = ((v.y - mu) * rstd * gm.y + bt.y) * dk;
        o.z = ((v.z - mu) * rstd * gm.z + bt.z) * dk;
        o.w = ((v.w - mu) * rstd * gm.w + bt.w) * dk;
    } else {
        o = v;
    }
    reinterpret_cast<float4*>(o32 + row * DD)[tid] = o;
    __half2* p = reinterpret_cast<__half2*>(o16 + row * DD) + tid * 2;
    p[0] = __floats2half2_rn(o.x, o.y);
    p[1] = __floats2half2_rn(o.z, o.w);
}

// ---------------- flash attention (Q tile 128, KV tiles 128, online softmax) ----
#define FLD 136                       // smem row stride in halves (272B, conflict-free)
#define FTILE (128 * FLD)             // halves per 128x128 tile
#define FSMEM (5 * FTILE * 2)         // bytes: Q + 2xK + 2xV

__global__ __launch_bounds__(256, 1)
void flash_kernel(const __half* __restrict__ QKV, __half* __restrict__ CTX) {
    extern __shared__ __half sm[];
    __half* Qs = sm;                       // [128][FLD]
    __half* Kb = sm + FTILE;               // 2 buffers
    __half* Vb = sm + 3 * FTILE;           // 2 buffers

    const int qt = blockIdx.x;
    const int h  = blockIdx.y;
    const int b  = blockIdx.z;
    const long base = (long)b * SS * 3 * DD + (long)h * HDIM;
    const __half* Qg = QKV + base;                 // row stride 3*DD
    const __half* Kg = QKV + base + DD;
    const __half* Vg = QKV + base + 2 * DD;

    const int tid = threadIdx.x, warp = tid >> 5, lane = tid & 31;
    const int g = lane >> 2, t = lane & 3;

    auto loadK = [&](int j, int buf) {
        __half* dst = Kb + buf * FTILE;
        #pragma unroll
        for (int i = 0; i < 8; i++) {
            int ch = tid + i * 256;
            int r = ch >> 4, o = (ch & 15) * 8;
            cp16(sptr(&dst[r * FLD + o]), Kg + (long)(j * 128 + r) * (3 * DD) + o);
        }
    };
    auto loadV = [&](int j, int buf) {
        __half* dst = Vb + buf * FTILE;
        #pragma unroll
        for (int i = 0; i < 8; i++) {
            int ch = tid + i * 256;
            int r = ch >> 4, o = (ch & 15) * 8;
            cp16(sptr(&dst[r * FLD + o]), Vg + (long)(j * 128 + r) * (3 * DD) + o);
        }
    };

    // stage Q, prefetch KV0, KV1
    #pragma unroll
    for (int i = 0; i < 8; i++) {
        int ch = tid + i * 256;
        int r = ch >> 4, o = (ch & 15) * 8;
        cp16(sptr(&Qs[r * FLD + o]), Qg + (long)(qt * 128 + r) * (3 * DD) + o);
    }
    cp_commit();
    loadK(0, 0); loadV(0, 0); cp_commit();
    loadK(1, 1); loadV(1, 1); cp_commit();

    asm volatile("cp.async.wait_group 2;\n");
    __syncthreads();

    // Q fragments (pre-scaled by 1/sqrt(hd))
    uint32_t qf[8][4];
    const __half2 sc2 = __float2half2_rn(0.08838834764831845f);
    #pragma unroll
    for (int kt = 0; kt < 8; kt++) {
        ldsm_x4(qf[kt], sptr(&Qs[(warp * 16 + (lane & 15)) * FLD + kt * 16 + (lane >> 4) * 8]));
        #pragma unroll
        for (int r = 0; r < 4; r++) {
            __half2 v = *reinterpret_cast<__half2*>(&qf[kt][r]);
            v = __hmul2(v, sc2);
            qf[kt][r] = *reinterpret_cast<uint32_t*>(&v);
        }
    }

    float m0 = -1e30f, m1 = -1e30f, l0 = 0.f, l1 = 0.f;
    float o[16][4];
    #pragma unroll
    for (int i = 0; i < 16; i++)
        #pragma unroll
        for (int r = 0; r < 4; r++) o[i][r] = 0.f;

    const int NKV = SS / 128;   // 16
    for (int j = 0; j < NKV; j++) {
        const int buf = j & 1;
        if (j < NKV - 1) asm volatile("cp.async.wait_group 1;\n");
        else             asm volatile("cp.async.wait_group 0;\n");
        __syncthreads();

        // ---- S = Qscaled @ K^T ----
        float s[16][4];
        #pragma unroll
        for (int i = 0; i < 16; i++)
            #pragma unroll
            for (int r = 0; r < 4; r++) s[i][r] = 0.f;
        const __half* Ksb = Kb + buf * FTILE;
        #pragma unroll
        for (int n2 = 0; n2 < 8; n2++) {
            #pragma unroll
            for (int kk = 0; kk < 8; kk++) {
                uint32_t bf[4];
                ldsm_x4(bf, sptr(&Ksb[(n2 * 16 + (lane & 7) + ((lane >> 4) << 3)) * FLD
                                      + kk * 16 + ((lane >> 3) & 1) * 8]));
                mma16816(s[2 * n2],     qf[kk], bf);
                mma16816(s[2 * n2 + 1], qf[kk], bf + 2);
            }
        }

        // ---- online softmax ----
        float mx0 = -1e30f, mx1 = -1e30f;
        #pragma unroll
        for (int i = 0; i < 16; i++) {
            mx0 = fmaxf(mx0, fmaxf(s[i][0], s[i][1]));
            mx1 = fmaxf(mx1, fmaxf(s[i][2], s[i][3]));
        }
        mx0 = fmaxf(mx0, __shfl_xor_sync(0xffffffffu, mx0, 1));
        mx0 = fmaxf(mx0, __shfl_xor_sync(0xffffffffu, mx0, 2));
        mx1 = fmaxf(mx1, __shfl_xor_sync(0xffffffffu, mx1, 1));
        mx1 = fmaxf(mx1, __shfl_xor_sync(0xffffffffu, mx1, 2));
        float nm0 = fmaxf(m0, mx0), nm1 = fmaxf(m1, mx1);
        float rs0 = __expf(m0 - nm0), rs1 = __expf(m1 - nm1);
        float sum0 = 0.f, sum1 = 0.f;
        #pragma unroll
        for (int i = 0; i < 16; i++) {
            s[i][0] = __expf(s[i][0] - nm0);
            s[i][1] = __expf(s[i][1] - nm0);
            s[i][2] = __expf(s[i][2] - nm1);
            s[i][3] = __expf(s[i][3] - nm1);
            sum0 += s[i][0] + s[i][1];
            sum1 += s[i][2] + s[i][3];
        }
        sum0 += __shfl_xor_sync(0xffffffffu, sum0, 1);
        sum0 += __shfl_xor_sync(0xffffffffu, sum0, 2);
        sum1 += __shfl_xor_sync(0xffffffffu, sum1, 1);
        sum1 += __shfl_xor_sync(0xffffffffu, sum1, 2);
        l0 = l0 * rs0 + sum0;
        l1 = l1 * rs1 + sum1;
        m0 = nm0; m1 = nm1;
        #pragma unroll
        for (int i = 0; i < 16; i++) {
            o[i][0] *= rs0; o[i][1] *= rs0;
            o[i][2] *= rs1; o[i][3] *= rs1;
        }

        // ---- O += P @ V ----
        const __half* Vsb = Vb + buf * FTILE;
        #pragma unroll
        for (int kt = 0; kt < 8; kt++) {
            uint32_t a[4];
            a[0] = packh2(s[2 * kt][0],     s[2 * kt][1]);
            a[1] = packh2(s[2 * kt][2],     s[2 * kt][3]);
            a[2] = packh2(s[2 * kt + 1][0], s[2 * kt + 1][1]);
            a[3] = packh2(s[2 * kt + 1][2], s[2 * kt + 1][3]);
            #pragma unroll
            for (int n2 = 0; n2 < 8; n2++) {
                uint32_t bf[4];
                ldsm_x4_t(bf, sptr(&Vsb[(kt * 16 + (lane & 15)) * FLD
                                        + n2 * 16 + (lane >> 4) * 8]));
                mma16816(o[2 * n2],     a, bf);
                mma16816(o[2 * n2 + 1], a, bf + 2);
            }
        }

        __syncthreads();
        if (j + 2 < NKV) { loadK(j + 2, buf); loadV(j + 2, buf); cp_commit(); }
    }

    // ---- epilogue: O /= l, write fp16 ctx ----
    float inv0 = 1.0f / l0, inv1 = 1.0f / l1;
    __half* Cp = CTX + ((long)b * SS + qt * 128 + warp * 16) * DD + h * HDIM;
    #pragma unroll
    for (int i = 0; i < 16; i++) {
        int col = i * 8 + 2 * t;
        *reinterpret_cast<__half2*>(&Cp[(long)g * DD + col]) =
            __floats2half2_rn(o[i][0] * inv0, o[i][1] * inv0);
        *reinterpret_cast<__half2*>(&Cp[(long)(g + 8) * DD + col]) =
            __floats2half2_rn(o[i][2] * inv1, o[i][3] * inv1);
    }
}

// ---------------- fp16 GEMM (ldmatrix + mma.m16n8k16 + cp.async pipeline) -------
#define BM 128
#define BN 128
#define BK 32
#define ALD 40

template<bool TRANSB>
__global__ __launch_bounds__(256, 2)
void hgemm(const __half* __restrict__ A, int lda,
           const __half* __restrict__ B, int ldb,
           int ldc,
           float* __restrict__ C32, __half* __restrict__ C16,
           const float* __restrict__ bias,
           const float* __restrict__ Res, int ldres,
           float alpha, int K)
{
    __shared__ alignas(16) __half As[2][BM * ALD];
    __shared__ alignas(16) __half Bs[2][BM * ALD];

    const int m0 = blockIdx.y * BM;
    const int n0 = blockIdx.x * BN;

    const int tid  = threadIdx.x;
    const int warp = tid >> 5, lane = tid & 31;
    const int g = lane >> 2, t = lane & 3;
    const int wm = (warp >> 2) * 64;
    const int wn = (warp & 3) * 32;

    float c[4][4][4];
    #pragma unroll
    for (int i = 0; i < 4; i++)
        #pragma unroll
        for (int j = 0; j < 4; j++)
            #pragma unroll
            for (int r = 0; r < 4; r++) c[i][j][r] = 0.f;

    auto loadA = [&](int st, int k0) {
        #pragma unroll
        for (int i = 0; i < 2; i++) {
            int ch = tid + i * 256;
            int r = ch >> 2, o = (ch & 3) * 8;
            cp16(sptr(&As[st][r * ALD + o]), A + (long)(m0 + r) * lda + k0 + o);
        }
    };
    auto loadB = [&](int st, int k0) {
        #pragma unroll
        for (int i = 0; i < 2; i++) {
            int ch = tid + i * 256;
            int r = ch >> 2, o = (ch & 3) * 8;
            cp16(sptr(&Bs[st][r * ALD + o]), B + (long)(n0 + r) * ldb + k0 + o);
        }
    };

    auto compute = [&](int st) {
        #pragma unroll
        for (int kk = 0; kk < BK; kk += 16) {
            uint32_t a[4][4];
            #pragma unroll
            for (int mi = 0; mi < 4; mi++)
                ldsm_x4(a[mi], sptr(&As[st][(wm + mi * 16 + (lane & 15)) * ALD
                                            + kk + (lane >> 4) * 8]));
            uint32_t b[2][4];
            #pragma unroll
            for (int nt = 0; nt < 2; nt++)
                ldsm_x4(b[nt], sptr(&Bs[st][(wn + nt * 16 + (lane & 7) + ((lane >> 4) << 3)) * ALD
                                            + kk + ((lane >> 3) & 1) * 8]));
            #pragma unroll
            for (int mi = 0; mi < 4; mi++)
                #pragma unroll
                for (int ni = 0; ni < 4; ni++)
                    mma16816(c[mi][ni], a[mi], &b[ni >> 1][(ni & 1) * 2]);
        }
    };

    const int KT = K / BK;
    loadA(0, 0); loadB(0, 0); cp_commit();
    int st = 0;
    for (int kt = 0; kt < KT; kt++) {
        if (kt + 1 < KT) {
            loadA(st ^ 1, (kt + 1) * BK); loadB(st ^ 1, (kt + 1) * BK); cp_commit();
            asm volatile("cp.async.wait_group 1;\n");
        } else {
            asm volatile("cp.async.wait_group 0;\n");
        }
        __syncthreads();
        compute(st);
        __syncthreads();
        st ^= 1;
    }

    #pragma unroll
    for (int mi = 0; mi < 4; mi++) {
        #pragma unroll
        for (int ni = 0; ni < 4; ni++) {
            int row0 = m0 + wm + mi * 16 + g;
            int col  = n0 + wn + ni * 8 + 2 * t;
            float2 v0, v1;
            v0.x = c[mi][ni][0] * alpha; v0.y = c[mi][ni][1] * alpha;
            v1.x = c[mi][ni][2] * alpha; v1.y = c[mi][ni][3] * alpha;
            if (bias) {
                float b0 = bias[col], b1 = bias[col + 1];
                v0.x += b0; v0.y += b1; v1.x += b0; v1.y += b1;
            }
            if (Res) {
                v0.x += Res[(long)row0 * ldres + col];
                v0.y += Res[(long)row0 * ldres + col + 1];
                v1.x += Res[(long)(row0 + 8) * ldres + col];
                v1.y += Res[(long)(row0 + 8) * ldres + col + 1];
            }
            if (C32) {
                *reinterpret_cast<float2*>(&C32[(long)row0 * ldc + col])       = v0;
                *reinterpret_cast<float2*>(&C32[(long)(row0 + 8) * ldc + col]) = v1;
            }
            if (C16) {
                *reinterpret_cast<__half2*>(&C16[(long)row0 * ldc + col])       = __floats2half2_rn(v0.x, v0.y);
                *reinterpret_cast<__half2*>(&C16[(long)(row0 + 8) * ldc + col]) = __floats2half2_rn(v1.x, v1.y);
            }
        }
    }
}

// ---------------- launch --------------------------------------------------------
extern "C" void kernel_launch(void* const* d_in, const int* in_sizes, int n_in,
                              void* d_out, int out_size) {
    const float* x      = (const float*)d_in[0];
    const int*   ts     = (const int*)  d_in[1];
    const float* gamma  = (const float*)d_in[2];
    const float* beta   = (const float*)d_in[3];
    const float* decay  = (const float*)d_in[4];
    const float* shiftW = (const float*)d_in[5];
    const float* shiftb = (const float*)d_in[6];
    const float* inW    = (const float*)d_in[7];
    const float* inb    = (const float*)d_in[8];
    const float* outW   = (const float*)d_in[9];
    const float* outb   = (const float*)d_in[10];
    float* out = (float*)d_out;

    const int T  = in_sizes[4];
    const int BS = in_sizes[0] / DD;       // 8192

    float *XLN32, *X232;
    __half *XLN16, *X216, *QKV16, *CTX16, *W16;
    cudaGetSymbolAddress((void**)&XLN32, g_XLN32);
    cudaGetSymbolAddress((void**)&X232,  g_X232);
    cudaGetSymbolAddress((void**)&XLN16, g_XLN16);
    cudaGetSymbolAddress((void**)&X216,  g_X216);
    cudaGetSymbolAddress((void**)&QKV16, g_QKV16);
    cudaGetSymbolAddress((void**)&CTX16, g_CTX16);
    cudaGetSymbolAddress((void**)&W16,   g_W16);

    __half* shW16 = W16;
    __half* inW16 = W16 + (size_t)1024 * 1024;
    __half* otW16 = W16 + (size_t)4 * 1024 * 1024;

    cudaFuncSetAttribute(flash_kernel, cudaFuncAttributeMaxDynamicSharedMemorySize, FSMEM);

    // 0) weights -> fp16
    f2h_kernel<<<(1024 * 1024 / 4 + 255) / 256, 256>>>(shiftW, shW16, 1024 * 1024 / 4);
    f2h_kernel<<<(3072 * 1024 / 4 + 255) / 256, 256>>>(inW,    inW16, 3072 * 1024 / 4);
    f2h_kernel<<<(1024 * 1024 / 4 + 255) / 256, 256>>>(outW,   otW16, 1024 * 1024 / 4);

    // 1) indexed LayerNorm
    ln_kernel<<<BS, 256>>>(x, ts, gamma, beta, decay, T, XLN32, XLN16);

    // 2) X2 = XLN + XLN @ shiftW^T + shiftb
    hgemm<true><<<dim3(DD / BN, BS / BM), 256>>>(
        XLN16, DD,  shW16, DD,  DD,  X232, X216,  shiftb,  XLN32, DD,  1.0f, DD);

    // 3) QKV = X2 @ inW^T + inb
    hgemm<true><<<dim3(3 * DD / BN, BS / BM), 256>>>(
        X216, DD,  inW16, DD,  3 * DD,  nullptr, QKV16,  inb,  nullptr, 0,  1.0f, DD);

    // 4) fused flash attention
    flash_kernel<<<dim3(SS / 128, NH, BB), 256, FSMEM>>>(QKV16, CTX16);

    // 5) out = X2 + CTX @ outW^T + outb
    hgemm<true><<<dim3(DD / BN, BS / BM), 256>>>(
        CTX16, DD,  otW16, DD,  DD,  out, nullptr,  outb,  X232, DD,  1.0f, DD);
}